// round 9
// baseline (speedup 1.0000x reference)
#include <cuda_runtime.h>

#define N_NODES  100000
#define N_EDGES  3200000
#define N_GRAPHS 1024
#define HID      64
#define NCLS     21
#define NBLK     391   // ceil(N_NODES / 256)

typedef unsigned long long ull;

// ---- scratch ----
__device__ __align__(128) int    g_deg [N_NODES];
__device__ __align__(128) int    g_cursor[N_NODES];
__device__ __align__(128) int    g_row [N_NODES];
__device__ __align__(128) int    g_bsum[NBLK];
__device__ __align__(128) int    g_csr [N_EDGES];     // src ids grouped by dst
__device__ __align__(128) float2 g_nf  [N_NODES];     // (mean1, x) per node
__device__ __align__(128) float  g_pool[N_GRAPHS * HID];
__device__ __align__(128) float  g_gcnt[N_GRAPHS];

__device__ __forceinline__ int clamp_node(int i) {
    i = i < 0 ? 0 : i;
    return i >= N_NODES ? N_NODES - 1 : i;
}

// ---- packed fp32x2 helpers ----
__device__ __forceinline__ ull fma2(ull a, ull b, ull c) {
    ull d; asm("fma.rn.f32x2 %0, %1, %2, %3;" : "=l"(d) : "l"(a), "l"(b), "l"(c)); return d;
}
__device__ __forceinline__ float2 unpk2(ull v) {
    float lo, hi; asm("mov.b64 {%0, %1}, %2;" : "=f"(lo), "=f"(hi) : "l"(v));
    return make_float2(lo, hi);
}

// ---- zero accumulators ----
__global__ void zero_kernel() {
    int i = blockIdx.x * blockDim.x + threadIdx.x;
    int stride = gridDim.x * blockDim.x;
    for (int j = i; j < N_NODES; j += stride) g_deg[j] = 0;
    for (int j = i; j < N_GRAPHS * HID; j += stride) g_pool[j] = 0.0f;
    for (int j = i; j < N_GRAPHS; j += stride) g_gcnt[j] = 0.0f;
}

// ---- hist: degree histogram (dst only) + fused graph-count histogram ----
__global__ void hist_kernel(const int* __restrict__ ei,
                            const int* __restrict__ batch) {
    int e = blockIdx.x * blockDim.x + threadIdx.x;
    if (e < N_NODES) {
        int b = batch[e];
        b = b < 0 ? 0 : (b >= N_GRAPHS ? N_GRAPHS - 1 : b);
        atomicAdd(&g_gcnt[b], 1.0f);
    }
    if (e >= N_EDGES) return;
    int d = clamp_node(ei[N_EDGES + e]);
    atomicAdd(&g_deg[d], 1);
}

// ---- scan A: per-block sums of degree ----
__global__ void scanA_kernel() {
    __shared__ int s[256];
    int t = threadIdx.x;
    int i = blockIdx.x * 256 + t;
    s[t] = (i < N_NODES) ? g_deg[i] : 0;
    __syncthreads();
    for (int off = 128; off > 0; off >>= 1) {
        if (t < off) s[t] += s[t + off];
        __syncthreads();
    }
    if (t == 0) g_bsum[blockIdx.x] = s[0];
}

// ---- scan C: block offset (in-block reduce of bsum) + local scan -> row, cursor ----
__global__ void scanC_kernel() {
    __shared__ int red[256];
    __shared__ int s[256];
    int t = threadIdx.x;
    int bid = blockIdx.x;

    int acc = 0;
    for (int j = t; j < NBLK; j += 256)
        if (j < bid) acc += g_bsum[j];
    red[t] = acc;
    int i = bid * 256 + t;
    int deg = (i < N_NODES) ? g_deg[i] : 0;
    s[t] = deg;
    __syncthreads();
    for (int off = 128; off > 0; off >>= 1) {
        if (t < off) red[t] += red[t + off];
        __syncthreads();
    }
    int boff = red[0];
    for (int off = 1; off < 256; off <<= 1) {
        int tmp = 0;
        if (t >= off) tmp = s[t - off];
        __syncthreads();
        if (t >= off) s[t] += tmp;
        __syncthreads();
    }
    if (i < N_NODES) {
        int r = boff + s[t] - deg;
        g_row[i] = r;
        g_cursor[i] = r;
    }
}

// ---- scatter: fill index CSR ----
__global__ void scatter_kernel(const int* __restrict__ ei) {
    int e = blockIdx.x * blockDim.x + threadIdx.x;
    if (e >= N_EDGES) return;
    int s = clamp_node(ei[e]);
    int d = clamp_node(ei[N_EDGES + e]);
    int pos = atomicAdd(&g_cursor[d], 1);
    g_csr[pos] = s;
}

// ---- nf: per-node (mean of neighbor x, own x). Warp per node. ----
__global__ void nf_kernel(const float* __restrict__ x) {
    int wid  = threadIdx.x >> 5;
    int lane = threadIdx.x & 31;
    int n = blockIdx.x * 8 + wid;
    if (n >= N_NODES) return;
    int start = g_row[n], deg = g_deg[n], end = start + deg;
    float sum = 0.0f;
    for (int idx = start + lane; idx < end; idx += 32)
        sum += x[g_csr[idx]];
#pragma unroll
    for (int o = 16; o > 0; o >>= 1)
        sum += __shfl_xor_sync(0xffffffffu, sum, o);
    if (lane == 0)
        g_nf[n] = make_float2(sum / fmaxf((float)deg, 1.0f), x[n]);
}

// ==== fused: agg2 (index CSR + on-the-fly h1) -> GEMM -> relu -> pool ====
#define A2STR 66   // float2 stride
#define SBSTR 68
__global__ __launch_bounds__(256, 4) void h2pool_gemm(
        const int* __restrict__ batch,
        const float* __restrict__ W2l,
        const float* __restrict__ b2,
        const float* __restrict__ W2r,
        const float* __restrict__ W1l,
        const float* __restrict__ b1,
        const float* __restrict__ W1r) {
    __shared__ __align__(16) float2 sA2[64 * A2STR];   // [k][node] duplicated {v,v}
    __shared__ __align__(16) float  sB[64 * SBSTR];    // [k][feat]
    __shared__ int    sBatch[64];
    __shared__ float2 sNF[64];

    int t    = threadIdx.x;
    int lane = t & 31;
    int wid  = t >> 5;
    int n0   = blockIdx.x * 64;
    int tx   = t & 15;
    int ty   = t >> 4;

    if (t < 64) {
        int n = n0 + t;
        int b = -1;
        float2 nf = make_float2(0.0f, 0.0f);
        if (n < N_NODES) {
            b = batch[n];
            b = b < 0 ? 0 : (b >= N_GRAPHS ? N_GRAPHS - 1 : b);
            nf = g_nf[n];
        }
        sBatch[t] = b;
        sNF[t] = nf;
    }

    // fill sB with W2l while phase A runs
#pragma unroll
    for (int i = 0; i < 16; i++) {
        int idx = t + i * 256;
        int f = idx & 63, k = idx >> 6;
        sB[k * SBSTR + f] = W2l[k * HID + f];
    }

    // ---- Phase A: per-warp neighbor-mean of h1, debranched (pad-corrected) ----
    {
        float wl0 = W1l[lane],      wr0 = W1r[lane],      bb0 = b1[lane];
        float wl1 = W1l[lane + 32], wr1 = W1r[lane + 32], bb1 = b1[lane + 32];
        float rp0 = fmaxf(bb0, 0.0f);   // h1 contribution of a zero-padded lane
        float rp1 = fmaxf(bb1, 0.0f);
#pragma unroll 1
        for (int r = 0; r < 8; r++) {
            int nl = wid * 8 + r;
            int n  = n0 + nl;
            float acc0 = 0.0f, acc1 = 0.0f;
            int deg = 0;
            if (n < N_NODES) {
                int start = g_row[n];
                deg = g_deg[n];
                int end = start + deg;
                int chunks = 0;
#pragma unroll 1
                for (int j = start; j < end; j += 32) {
                    int idx = j + lane;
                    float2 v = make_float2(0.0f, 0.0f);
                    if (idx < end) {
                        int s = g_csr[idx];
                        v = g_nf[s];
                    }
                    chunks++;
#pragma unroll
                    for (int jj = 0; jj < 32; jj++) {
                        float a  = __shfl_sync(0xffffffffu, v.x, jj);
                        float xx = __shfl_sync(0xffffffffu, v.y, jj);
                        acc0 += fmaxf(fmaf(a, wl0, fmaf(xx, wr0, bb0)), 0.0f);
                        acc1 += fmaxf(fmaf(a, wl1, fmaf(xx, wr1, bb1)), 0.0f);
                    }
                }
                // padded lanes contributed relu(b1[f]) each; remove them.
                float npad = (float)(chunks * 32 - deg);
                acc0 -= npad * rp0;
                acc1 -= npad * rp1;
            }
            float inv = 1.0f / fmaxf((float)deg, 1.0f);
            float v0 = acc0 * inv, v1 = acc1 * inv;
            sA2[lane * A2STR + nl]        = make_float2(v0, v0);
            sA2[(lane + 32) * A2STR + nl] = make_float2(v1, v1);
        }
    }
    __syncthreads();

    // ---- Phase B: GEMM, 2 K-chunks, packed f32x2 FMA, duplicated-a tiles ----
    ull acc2[4][2] = {};
#pragma unroll
    for (int ch = 0; ch < 2; ch++) {
#pragma unroll
        for (int k = 0; k < 64; k++) {
            ulonglong2 a01 = *(const ulonglong2*)&sA2[k * A2STR + ty * 4];
            ulonglong2 a23 = *(const ulonglong2*)&sA2[k * A2STR + ty * 4 + 2];
            ulonglong2 b   = *(const ulonglong2*)&sB[k * SBSTR + tx * 4];
            acc2[0][0] = fma2(a01.x, b.x, acc2[0][0]); acc2[0][1] = fma2(a01.x, b.y, acc2[0][1]);
            acc2[1][0] = fma2(a01.y, b.x, acc2[1][0]); acc2[1][1] = fma2(a01.y, b.y, acc2[1][1]);
            acc2[2][0] = fma2(a23.x, b.x, acc2[2][0]); acc2[2][1] = fma2(a23.x, b.y, acc2[2][1]);
            acc2[3][0] = fma2(a23.y, b.x, acc2[3][0]); acc2[3][1] = fma2(a23.y, b.y, acc2[3][1]);
        }
        __syncthreads();
        if (ch == 0) {
            // refill sA2 with on-the-fly h1 (duplicated), sB with W2r
#pragma unroll
            for (int i = 0; i < 16; i++) {
                int idx = t + i * 256;
                int f = idx & 63, n = idx >> 6;
                float2 nf = sNF[n];
                float v = fmaxf(fmaf(nf.x, W1l[f], fmaf(nf.y, W1r[f], b1[f])), 0.0f);
                if (n0 + n >= N_NODES) v = 0.0f;
                sA2[f * A2STR + n] = make_float2(v, v);
            }
#pragma unroll
            for (int i = 0; i < 16; i++) {
                int idx = t + i * 256;
                int f = idx & 63, k = idx >> 6;
                sB[k * SBSTR + f] = W2r[k * HID + f];
            }
            __syncthreads();
        }
    }

    // ---- Phase C: bias + relu -> stage h2 into sB [node][feat], then pool ----
#pragma unroll
    for (int i = 0; i < 4; i++) {
        float2 p0 = unpk2(acc2[i][0]);
        float2 p1 = unpk2(acc2[i][1]);
        int nrow = (ty * 4 + i) * SBSTR + tx * 4;
        sB[nrow + 0] = fmaxf(p0.x + b2[tx * 4 + 0], 0.0f);
        sB[nrow + 1] = fmaxf(p0.y + b2[tx * 4 + 1], 0.0f);
        sB[nrow + 2] = fmaxf(p1.x + b2[tx * 4 + 2], 0.0f);
        sB[nrow + 3] = fmaxf(p1.y + b2[tx * 4 + 3], 0.0f);
    }
    __syncthreads();

    {
        int f = t & 63;
        int g = t >> 6;
        int cur = -2;
        float racc = 0.0f;
#pragma unroll
        for (int i = 0; i < 16; i++) {
            int n = g * 16 + i;
            int b = sBatch[n];
            if (b != cur) {
                if (cur >= 0) atomicAdd(&g_pool[cur * HID + f], racc);
                racc = 0.0f;
                cur = b;
            }
            if (b >= 0) racc += sB[n * SBSTR + f];
        }
        if (cur >= 0) atomicAdd(&g_pool[cur * HID + f], racc);
    }
}

// ---- classifier ----
__global__ void final_kernel(const float* __restrict__ Wc,
                             const float* __restrict__ bc,
                             float* __restrict__ out) {
    int g = blockIdx.x;
    int cid = threadIdx.x;
    if (cid >= NCLS) return;
    float inv = 1.0f / fmaxf(g_gcnt[g], 1.0f);
    float acc = bc[cid];
#pragma unroll
    for (int k = 0; k < HID; k++) {
        acc += g_pool[g * HID + k] * inv * Wc[k * NCLS + cid];
    }
    out[g * NCLS + cid] = acc;
}

extern "C" void kernel_launch(void* const* d_in, const int* in_sizes, int n_in,
                              void* d_out, int out_size) {
    const float* x    = (const float*)d_in[0];
    const int*   ei   = (const int*)d_in[1];
    const int*   bat  = (const int*)d_in[2];
    const float* W1l  = (const float*)d_in[3];
    const float* b1   = (const float*)d_in[4];
    const float* W1r  = (const float*)d_in[5];
    const float* W2l  = (const float*)d_in[6];
    const float* b2   = (const float*)d_in[7];
    const float* W2r  = (const float*)d_in[8];
    const float* Wc   = (const float*)d_in[9];
    const float* bc   = (const float*)d_in[10];
    float*       out  = (float*)d_out;

    (void)in_sizes; (void)n_in; (void)out_size;

    zero_kernel<<<1024, 256>>>();
    hist_kernel<<<(N_EDGES + 255) / 256, 256>>>(ei, bat);
    scanA_kernel<<<NBLK, 256>>>();
    scanC_kernel<<<NBLK, 256>>>();
    scatter_kernel<<<(N_EDGES + 255) / 256, 256>>>(ei);
    nf_kernel<<<12500, 256>>>(x);
    h2pool_gemm<<<(N_NODES + 63) / 64, 256>>>(bat, W2l, b2, W2r, W1l, b1, W1r);
    final_kernel<<<N_GRAPHS, 32>>>(Wc, bc, out);
}

// round 10
// speedup vs baseline: 1.1093x; 1.1093x over previous
#include <cuda_runtime.h>

#define N_NODES  100000
#define N_EDGES  3200000
#define N_GRAPHS 1024
#define HID      64
#define NCLS     21
#define NBLK     391   // ceil(N_NODES / 256)

typedef unsigned long long ull;

// ---- scratch ----
__device__ __align__(128) int    g_deg [N_NODES];
__device__ __align__(128) int    g_cursor[N_NODES];
__device__ __align__(128) int    g_row [N_NODES];
__device__ __align__(128) float  g_agg1[N_NODES];
__device__ __align__(128) int    g_bsum[NBLK];
__device__ __align__(128) int    g_csr [N_EDGES];     // src ids grouped by dst
__device__ __align__(128) float2 g_nf  [N_NODES];     // (mean1, x) per node
__device__ __align__(128) float  g_pool[N_GRAPHS * HID];
__device__ __align__(128) float  g_gcnt[N_GRAPHS];

__device__ __forceinline__ int clamp_node(int i) {
    i = i < 0 ? 0 : i;
    return i >= N_NODES ? N_NODES - 1 : i;
}

// ---- packed fp32x2 helpers ----
__device__ __forceinline__ ull pk2(float lo, float hi) {
    ull d; asm("mov.b64 %0, {%1, %2};" : "=l"(d) : "f"(lo), "f"(hi)); return d;
}
__device__ __forceinline__ ull fma2(ull a, ull b, ull c) {
    ull d; asm("fma.rn.f32x2 %0, %1, %2, %3;" : "=l"(d) : "l"(a), "l"(b), "l"(c)); return d;
}
__device__ __forceinline__ float2 unpk2(ull v) {
    float lo, hi; asm("mov.b64 {%0, %1}, %2;" : "=f"(lo), "=f"(hi) : "l"(v));
    return make_float2(lo, hi);
}

// ---- zero accumulators ----
__global__ void zero_kernel() {
    int i = blockIdx.x * blockDim.x + threadIdx.x;
    int stride = gridDim.x * blockDim.x;
    for (int j = i; j < N_NODES; j += stride) { g_deg[j] = 0; g_agg1[j] = 0.0f; }
    for (int j = i; j < N_GRAPHS * HID; j += stride) g_pool[j] = 0.0f;
    for (int j = i; j < N_GRAPHS; j += stride) g_gcnt[j] = 0.0f;
}

// ---- hist: degree + layer-1 scalar sum + graph-count histogram ----
__global__ void hist_kernel(const int* __restrict__ ei,
                            const int* __restrict__ batch,
                            const float* __restrict__ x) {
    int e = blockIdx.x * blockDim.x + threadIdx.x;
    if (e < N_NODES) {
        int b = batch[e];
        b = b < 0 ? 0 : (b >= N_GRAPHS ? N_GRAPHS - 1 : b);
        atomicAdd(&g_gcnt[b], 1.0f);
    }
    if (e >= N_EDGES) return;
    int s = clamp_node(ei[e]);
    int d = clamp_node(ei[N_EDGES + e]);
    atomicAdd(&g_deg[d], 1);
    atomicAdd(&g_agg1[d], x[s]);
}

// ---- scan A: per-block sums of degree ----
__global__ void scanA_kernel() {
    __shared__ int s[256];
    int t = threadIdx.x;
    int i = blockIdx.x * 256 + t;
    s[t] = (i < N_NODES) ? g_deg[i] : 0;
    __syncthreads();
    for (int off = 128; off > 0; off >>= 1) {
        if (t < off) s[t] += s[t + off];
        __syncthreads();
    }
    if (t == 0) g_bsum[blockIdx.x] = s[0];
}

// ---- scan C: block offset + local scan -> row, cursor; fused elementwise nf ----
__global__ void scanC_kernel(const float* __restrict__ x) {
    __shared__ int red[256];
    __shared__ int s[256];
    int t = threadIdx.x;
    int bid = blockIdx.x;

    int acc = 0;
    for (int j = t; j < NBLK; j += 256)
        if (j < bid) acc += g_bsum[j];
    red[t] = acc;
    int i = bid * 256 + t;
    int deg = (i < N_NODES) ? g_deg[i] : 0;
    s[t] = deg;
    __syncthreads();
    for (int off = 128; off > 0; off >>= 1) {
        if (t < off) red[t] += red[t + off];
        __syncthreads();
    }
    int boff = red[0];
    for (int off = 1; off < 256; off <<= 1) {
        int tmp = 0;
        if (t >= off) tmp = s[t - off];
        __syncthreads();
        if (t >= off) s[t] += tmp;
        __syncthreads();
    }
    if (i < N_NODES) {
        int r = boff + s[t] - deg;
        g_row[i] = r;
        g_cursor[i] = r;
        g_nf[i] = make_float2(g_agg1[i] / fmaxf((float)deg, 1.0f), x[i]);
    }
}

// ---- scatter: fill index CSR ----
__global__ void scatter_kernel(const int* __restrict__ ei) {
    int e = blockIdx.x * blockDim.x + threadIdx.x;
    if (e >= N_EDGES) return;
    int s = clamp_node(ei[e]);
    int d = clamp_node(ei[N_EDGES + e]);
    int pos = atomicAdd(&g_cursor[d], 1);
    g_csr[pos] = s;
}

// ==== fused: agg2 (index CSR + on-the-fly h1) -> GEMM -> relu -> pool ====
#define SASTR 68
__global__ __launch_bounds__(256) void h2pool_gemm(
        const int* __restrict__ batch,
        const float* __restrict__ W2l,
        const float* __restrict__ b2,
        const float* __restrict__ W2r,
        const float* __restrict__ W1l,
        const float* __restrict__ b1,
        const float* __restrict__ W1r) {
    __shared__ __align__(16) float sA[64 * SASTR];  // [k][node]
    __shared__ __align__(16) float sB[64 * SASTR];  // [k][feat]
    __shared__ int    sBatch[64];
    __shared__ float2 sNF[64];

    int t    = threadIdx.x;
    int lane = t & 31;
    int wid  = t >> 5;
    int n0   = blockIdx.x * 64;
    int tx   = t & 15;
    int ty   = t >> 4;

    if (t < 64) {
        int n = n0 + t;
        int b = -1;
        float2 nf = make_float2(0.0f, 0.0f);
        if (n < N_NODES) {
            b = batch[n];
            b = b < 0 ? 0 : (b >= N_GRAPHS ? N_GRAPHS - 1 : b);
            nf = g_nf[n];
        }
        sBatch[t] = b;
        sNF[t] = nf;
    }

    // fill sB with W2l while phase A runs
#pragma unroll
    for (int i = 0; i < 16; i++) {
        int idx = t + i * 256;
        int f = idx & 63, k = idx >> 6;
        sB[k * SASTR + f] = W2l[k * HID + f];
    }

    // ---- Phase A: per-warp neighbor-mean of h1 (uniform tail + prefetch) ----
    {
        float wl0 = W1l[lane],      wr0 = W1r[lane],      bb0 = b1[lane];
        float wl1 = W1l[lane + 32], wr1 = W1r[lane + 32], bb1 = b1[lane + 32];
#pragma unroll 1
        for (int r = 0; r < 8; r++) {
            int nl = wid * 8 + r;
            int n  = n0 + nl;
            float acc0 = 0.0f, acc1 = 0.0f;
            int deg = 0;
            if (n < N_NODES) {
                int start = g_row[n];
                deg = g_deg[n];
                int end = start + deg;
                if (deg > 0) {
                    // prime first chunk
                    int idx0 = start + lane;
                    int s0 = (idx0 < end) ? g_csr[idx0] : 0;
                    float2 vcur = g_nf[s0];
#pragma unroll 1
                    for (int j = start; j < end; j += 32) {
                        // prefetch next chunk before consuming current
                        float2 vnext = make_float2(0.0f, 0.0f);
                        if (j + 32 < end) {
                            int idx2 = j + 32 + lane;
                            int s2 = (idx2 < end) ? g_csr[idx2] : 0;
                            vnext = g_nf[s2];
                        }
                        int m = end - j; if (m > 32) m = 32;   // warp-uniform
                        if (m == 32) {
#pragma unroll
                            for (int jj = 0; jj < 32; jj++) {
                                float a  = __shfl_sync(0xffffffffu, vcur.x, jj);
                                float xx = __shfl_sync(0xffffffffu, vcur.y, jj);
                                acc0 += fmaxf(fmaf(a, wl0, fmaf(xx, wr0, bb0)), 0.0f);
                                acc1 += fmaxf(fmaf(a, wl1, fmaf(xx, wr1, bb1)), 0.0f);
                            }
                        } else {
                            for (int jj = 0; jj < m; jj++) {
                                float a  = __shfl_sync(0xffffffffu, vcur.x, jj);
                                float xx = __shfl_sync(0xffffffffu, vcur.y, jj);
                                acc0 += fmaxf(fmaf(a, wl0, fmaf(xx, wr0, bb0)), 0.0f);
                                acc1 += fmaxf(fmaf(a, wl1, fmaf(xx, wr1, bb1)), 0.0f);
                            }
                        }
                        vcur = vnext;
                    }
                }
            }
            float inv = 1.0f / fmaxf((float)deg, 1.0f);
            sA[lane * SASTR + nl]        = acc0 * inv;
            sA[(lane + 32) * SASTR + nl] = acc1 * inv;
        }
    }
    __syncthreads();

    // ---- Phase B: GEMM, 2 K-chunks, packed f32x2 FMA ----
    ull acc2[4][2] = {};
#pragma unroll
    for (int ch = 0; ch < 2; ch++) {
#pragma unroll
        for (int k = 0; k < 64; k++) {
            float4 a = *(const float4*)&sA[k * SASTR + ty * 4];
            ulonglong2 b = *(const ulonglong2*)&sB[k * SASTR + tx * 4];
            ull a0 = pk2(a.x, a.x), a1 = pk2(a.y, a.y);
            ull a2 = pk2(a.z, a.z), a3 = pk2(a.w, a.w);
            acc2[0][0] = fma2(a0, b.x, acc2[0][0]); acc2[0][1] = fma2(a0, b.y, acc2[0][1]);
            acc2[1][0] = fma2(a1, b.x, acc2[1][0]); acc2[1][1] = fma2(a1, b.y, acc2[1][1]);
            acc2[2][0] = fma2(a2, b.x, acc2[2][0]); acc2[2][1] = fma2(a2, b.y, acc2[2][1]);
            acc2[3][0] = fma2(a3, b.x, acc2[3][0]); acc2[3][1] = fma2(a3, b.y, acc2[3][1]);
        }
        __syncthreads();
        if (ch == 0) {
            // refill sA with on-the-fly h1, sB with W2r
#pragma unroll
            for (int i = 0; i < 16; i++) {
                int idx = t + i * 256;
                int f = idx & 63, n = idx >> 6;
                float2 nf = sNF[n];
                float v = fmaxf(fmaf(nf.x, W1l[f], fmaf(nf.y, W1r[f], b1[f])), 0.0f);
                if (n0 + n >= N_NODES) v = 0.0f;
                sA[f * SASTR + n] = v;
            }
#pragma unroll
            for (int i = 0; i < 16; i++) {
                int idx = t + i * 256;
                int f = idx & 63, k = idx >> 6;
                sB[k * SASTR + f] = W2r[k * HID + f];
            }
            __syncthreads();
        }
    }

    // ---- Phase C: bias + relu -> stage h2 into sA [node][feat], then pool ----
#pragma unroll
    for (int i = 0; i < 4; i++) {
        float2 p0 = unpk2(acc2[i][0]);
        float2 p1 = unpk2(acc2[i][1]);
        int nrow = (ty * 4 + i) * SASTR + tx * 4;
        sA[nrow + 0] = fmaxf(p0.x + b2[tx * 4 + 0], 0.0f);
        sA[nrow + 1] = fmaxf(p0.y + b2[tx * 4 + 1], 0.0f);
        sA[nrow + 2] = fmaxf(p1.x + b2[tx * 4 + 2], 0.0f);
        sA[nrow + 3] = fmaxf(p1.y + b2[tx * 4 + 3], 0.0f);
    }
    __syncthreads();

    {
        int f = t & 63;
        int g = t >> 6;
        int cur = -2;
        float racc = 0.0f;
#pragma unroll
        for (int i = 0; i < 16; i++) {
            int n = g * 16 + i;
            int b = sBatch[n];
            if (b != cur) {
                if (cur >= 0) atomicAdd(&g_pool[cur * HID + f], racc);
                racc = 0.0f;
                cur = b;
            }
            if (b >= 0) racc += sA[n * SASTR + f];
        }
        if (cur >= 0) atomicAdd(&g_pool[cur * HID + f], racc);
    }
}

// ---- classifier ----
__global__ void final_kernel(const float* __restrict__ Wc,
                             const float* __restrict__ bc,
                             float* __restrict__ out) {
    int g = blockIdx.x;
    int cid = threadIdx.x;
    if (cid >= NCLS) return;
    float inv = 1.0f / fmaxf(g_gcnt[g], 1.0f);
    float acc = bc[cid];
#pragma unroll
    for (int k = 0; k < HID; k++) {
        acc += g_pool[g * HID + k] * inv * Wc[k * NCLS + cid];
    }
    out[g * NCLS + cid] = acc;
}

extern "C" void kernel_launch(void* const* d_in, const int* in_sizes, int n_in,
                              void* d_out, int out_size) {
    const float* x    = (const float*)d_in[0];
    const int*   ei   = (const int*)d_in[1];
    const int*   bat  = (const int*)d_in[2];
    const float* W1l  = (const float*)d_in[3];
    const float* b1   = (const float*)d_in[4];
    const float* W1r  = (const float*)d_in[5];
    const float* W2l  = (const float*)d_in[6];
    const float* b2   = (const float*)d_in[7];
    const float* W2r  = (const float*)d_in[8];
    const float* Wc   = (const float*)d_in[9];
    const float* bc   = (const float*)d_in[10];
    float*       out  = (float*)d_out;

    (void)in_sizes; (void)n_in; (void)out_size;

    zero_kernel<<<1024, 256>>>();
    hist_kernel<<<(N_EDGES + 255) / 256, 256>>>(ei, bat, x);
    scanA_kernel<<<NBLK, 256>>>();
    scanC_kernel<<<NBLK, 256>>>(x);
    scatter_kernel<<<(N_EDGES + 255) / 256, 256>>>(ei);
    h2pool_gemm<<<(N_NODES + 63) / 64, 256>>>(bat, W2l, b2, W2r, W1l, b1, W1r);
    final_kernel<<<N_GRAPHS, 32>>>(Wc, bc, out);
}

// round 11
// speedup vs baseline: 1.1210x; 1.0105x over previous
#include <cuda_runtime.h>

#define N_NODES  100000
#define N_EDGES  3200000
#define N_GRAPHS 1024
#define HID      64
#define NCLS     21
#define NBLK     391   // ceil(N_NODES / 256)

typedef unsigned long long ull;

// ---- scratch (zero-init at load; every replay restores zeros in final_kernel) ----
__device__ __align__(128) int    g_deg [N_NODES];
__device__ __align__(128) int    g_cursor[N_NODES];
__device__ __align__(128) int    g_row [N_NODES];
__device__ __align__(128) float  g_agg1[N_NODES];
__device__ __align__(128) int    g_alloc;             // CSR bump allocator
__device__ __align__(128) int    g_csr [N_EDGES];     // src ids grouped by dst
__device__ __align__(128) float2 g_nf  [N_NODES];     // (mean1, x) per node
__device__ __align__(128) float  g_pool[N_GRAPHS * HID];
__device__ __align__(128) float  g_gcnt[N_GRAPHS];

__device__ __forceinline__ int clamp_node(int i) {
    i = i < 0 ? 0 : i;
    return i >= N_NODES ? N_NODES - 1 : i;
}

// ---- packed fp32x2 helpers ----
__device__ __forceinline__ ull pk2(float lo, float hi) {
    ull d; asm("mov.b64 %0, {%1, %2};" : "=l"(d) : "f"(lo), "f"(hi)); return d;
}
__device__ __forceinline__ ull fma2(ull a, ull b, ull c) {
    ull d; asm("fma.rn.f32x2 %0, %1, %2, %3;" : "=l"(d) : "l"(a), "l"(b), "l"(c)); return d;
}
__device__ __forceinline__ float2 unpk2(ull v) {
    float lo, hi; asm("mov.b64 {%0, %1}, %2;" : "=f"(lo), "=f"(hi) : "l"(v));
    return make_float2(lo, hi);
}

// ---- #1 hist: degree + layer-1 scalar sum + graph-count histogram ----
__global__ void hist_kernel(const int* __restrict__ ei,
                            const int* __restrict__ batch,
                            const float* __restrict__ x) {
    int e = blockIdx.x * blockDim.x + threadIdx.x;
    if (e < N_NODES) {
        int b = batch[e];
        b = b < 0 ? 0 : (b >= N_GRAPHS ? N_GRAPHS - 1 : b);
        atomicAdd(&g_gcnt[b], 1.0f);
    }
    if (e >= N_EDGES) return;
    int s = clamp_node(ei[e]);
    int d = clamp_node(ei[N_EDGES + e]);
    atomicAdd(&g_deg[d], 1);
    atomicAdd(&g_agg1[d], x[s]);
}

// ---- #2 scan: block-local scan + atomic bump allocation (order-free CSR) ----
//      also emits nf = (agg1/deg, x) elementwise.
__global__ void scan_alloc_kernel(const float* __restrict__ x) {
    __shared__ int s[256];
    __shared__ int base;
    int t = threadIdx.x;
    int i = blockIdx.x * 256 + t;
    int deg = (i < N_NODES) ? g_deg[i] : 0;
    s[t] = deg;
    __syncthreads();
    for (int off = 1; off < 256; off <<= 1) {
        int tmp = 0;
        if (t >= off) tmp = s[t - off];
        __syncthreads();
        if (t >= off) s[t] += tmp;
        __syncthreads();
    }
    if (t == 255) base = atomicAdd(&g_alloc, s[255]);
    __syncthreads();
    if (i < N_NODES) {
        int r = base + s[t] - deg;    // exclusive start within this block's chunk
        g_row[i] = r;
        g_cursor[i] = r;
        g_nf[i] = make_float2(g_agg1[i] / fmaxf((float)deg, 1.0f), x[i]);
    }
}

// ---- #3 scatter: fill index CSR ----
__global__ void scatter_kernel(const int* __restrict__ ei) {
    int e = blockIdx.x * blockDim.x + threadIdx.x;
    if (e >= N_EDGES) return;
    int s = clamp_node(ei[e]);
    int d = clamp_node(ei[N_EDGES + e]);
    int pos = atomicAdd(&g_cursor[d], 1);
    g_csr[pos] = s;
}

// ==== #4 fused: agg2 (index CSR + on-the-fly h1) -> GEMM -> relu -> pool ====
#define SASTR 68
__global__ __launch_bounds__(256) void h2pool_gemm(
        const int* __restrict__ batch,
        const float* __restrict__ W2l,
        const float* __restrict__ b2,
        const float* __restrict__ W2r,
        const float* __restrict__ W1l,
        const float* __restrict__ b1,
        const float* __restrict__ W1r) {
    __shared__ __align__(16) float sA[64 * SASTR];  // [k][node]
    __shared__ __align__(16) float sB[64 * SASTR];  // [k][feat]
    __shared__ int    sBatch[64];
    __shared__ float2 sNF[64];

    int t    = threadIdx.x;
    int lane = t & 31;
    int wid  = t >> 5;
    int n0   = blockIdx.x * 64;
    int tx   = t & 15;
    int ty   = t >> 4;

    if (t < 64) {
        int n = n0 + t;
        int b = -1;
        float2 nf = make_float2(0.0f, 0.0f);
        if (n < N_NODES) {
            b = batch[n];
            b = b < 0 ? 0 : (b >= N_GRAPHS ? N_GRAPHS - 1 : b);
            nf = g_nf[n];
        }
        sBatch[t] = b;
        sNF[t] = nf;
    }

    // fill sB with W2l while phase A runs
#pragma unroll
    for (int i = 0; i < 16; i++) {
        int idx = t + i * 256;
        int f = idx & 63, k = idx >> 6;
        sB[k * SASTR + f] = W2l[k * HID + f];
    }

    // ---- Phase A: per-warp neighbor-mean of h1 (uniform tail + prefetch) ----
    {
        float wl0 = W1l[lane],      wr0 = W1r[lane],      bb0 = b1[lane];
        float wl1 = W1l[lane + 32], wr1 = W1r[lane + 32], bb1 = b1[lane + 32];
#pragma unroll 1
        for (int r = 0; r < 8; r++) {
            int nl = wid * 8 + r;
            int n  = n0 + nl;
            float acc0 = 0.0f, acc1 = 0.0f;
            int deg = 0;
            if (n < N_NODES) {
                int start = g_row[n];
                deg = g_deg[n];
                int end = start + deg;
                if (deg > 0) {
                    int idx0 = start + lane;
                    int s0 = (idx0 < end) ? g_csr[idx0] : 0;
                    float2 vcur = g_nf[s0];
#pragma unroll 1
                    for (int j = start; j < end; j += 32) {
                        float2 vnext = make_float2(0.0f, 0.0f);
                        if (j + 32 < end) {
                            int idx2 = j + 32 + lane;
                            int s2 = (idx2 < end) ? g_csr[idx2] : 0;
                            vnext = g_nf[s2];
                        }
                        int m = end - j; if (m > 32) m = 32;   // warp-uniform
                        if (m == 32) {
#pragma unroll
                            for (int jj = 0; jj < 32; jj++) {
                                float a  = __shfl_sync(0xffffffffu, vcur.x, jj);
                                float xx = __shfl_sync(0xffffffffu, vcur.y, jj);
                                acc0 += fmaxf(fmaf(a, wl0, fmaf(xx, wr0, bb0)), 0.0f);
                                acc1 += fmaxf(fmaf(a, wl1, fmaf(xx, wr1, bb1)), 0.0f);
                            }
                        } else {
                            for (int jj = 0; jj < m; jj++) {
                                float a  = __shfl_sync(0xffffffffu, vcur.x, jj);
                                float xx = __shfl_sync(0xffffffffu, vcur.y, jj);
                                acc0 += fmaxf(fmaf(a, wl0, fmaf(xx, wr0, bb0)), 0.0f);
                                acc1 += fmaxf(fmaf(a, wl1, fmaf(xx, wr1, bb1)), 0.0f);
                            }
                        }
                        vcur = vnext;
                    }
                }
            }
            float inv = 1.0f / fmaxf((float)deg, 1.0f);
            sA[lane * SASTR + nl]        = acc0 * inv;
            sA[(lane + 32) * SASTR + nl] = acc1 * inv;
        }
    }
    __syncthreads();

    // ---- Phase B: GEMM, 2 K-chunks, packed f32x2 FMA ----
    ull acc2[4][2] = {};
#pragma unroll
    for (int ch = 0; ch < 2; ch++) {
#pragma unroll
        for (int k = 0; k < 64; k++) {
            float4 a = *(const float4*)&sA[k * SASTR + ty * 4];
            ulonglong2 b = *(const ulonglong2*)&sB[k * SASTR + tx * 4];
            ull a0 = pk2(a.x, a.x), a1 = pk2(a.y, a.y);
            ull a2 = pk2(a.z, a.z), a3 = pk2(a.w, a.w);
            acc2[0][0] = fma2(a0, b.x, acc2[0][0]); acc2[0][1] = fma2(a0, b.y, acc2[0][1]);
            acc2[1][0] = fma2(a1, b.x, acc2[1][0]); acc2[1][1] = fma2(a1, b.y, acc2[1][1]);
            acc2[2][0] = fma2(a2, b.x, acc2[2][0]); acc2[2][1] = fma2(a2, b.y, acc2[2][1]);
            acc2[3][0] = fma2(a3, b.x, acc2[3][0]); acc2[3][1] = fma2(a3, b.y, acc2[3][1]);
        }
        __syncthreads();
        if (ch == 0) {
#pragma unroll
            for (int i = 0; i < 16; i++) {
                int idx = t + i * 256;
                int f = idx & 63, n = idx >> 6;
                float2 nf = sNF[n];
                float v = fmaxf(fmaf(nf.x, W1l[f], fmaf(nf.y, W1r[f], b1[f])), 0.0f);
                if (n0 + n >= N_NODES) v = 0.0f;
                sA[f * SASTR + n] = v;
            }
#pragma unroll
            for (int i = 0; i < 16; i++) {
                int idx = t + i * 256;
                int f = idx & 63, k = idx >> 6;
                sB[k * SASTR + f] = W2r[k * HID + f];
            }
            __syncthreads();
        }
    }

    // ---- Phase C: bias + relu -> stage h2 into sA [node][feat], then pool ----
#pragma unroll
    for (int i = 0; i < 4; i++) {
        float2 p0 = unpk2(acc2[i][0]);
        float2 p1 = unpk2(acc2[i][1]);
        int nrow = (ty * 4 + i) * SASTR + tx * 4;
        sA[nrow + 0] = fmaxf(p0.x + b2[tx * 4 + 0], 0.0f);
        sA[nrow + 1] = fmaxf(p0.y + b2[tx * 4 + 1], 0.0f);
        sA[nrow + 2] = fmaxf(p1.x + b2[tx * 4 + 2], 0.0f);
        sA[nrow + 3] = fmaxf(p1.y + b2[tx * 4 + 3], 0.0f);
    }
    __syncthreads();

    {
        int f = t & 63;
        int g = t >> 6;
        int cur = -2;
        float racc = 0.0f;
#pragma unroll
        for (int i = 0; i < 16; i++) {
            int n = g * 16 + i;
            int b = sBatch[n];
            if (b != cur) {
                if (cur >= 0) atomicAdd(&g_pool[cur * HID + f], racc);
                racc = 0.0f;
                cur = b;
            }
            if (b >= 0) racc += sA[n * SASTR + f];
        }
        if (cur >= 0) atomicAdd(&g_pool[cur * HID + f], racc);
    }
}

// ---- #5 classifier + restore-zeros for next replay ----
__global__ void final_kernel(const float* __restrict__ Wc,
                             const float* __restrict__ bc,
                             float* __restrict__ out) {
    int g = blockIdx.x;
    int lt = threadIdx.x;     // 32 threads

    // classifier (threads with lt < NCLS)
    if (lt < NCLS) {
        float inv = 1.0f / fmaxf(g_gcnt[g], 1.0f);
        float acc = bc[lt];
#pragma unroll
        for (int k = 0; k < HID; k++) {
            acc += g_pool[g * HID + k] * inv * Wc[k * NCLS + lt];
        }
        out[g * NCLS + lt] = acc;
    }
    __syncwarp();   // all reads of g_pool/g_gcnt row done before zeroing

    // zero own pool row + gcnt
#pragma unroll
    for (int k = lt; k < HID; k += 32) g_pool[g * HID + k] = 0.0f;
    if (lt == 0) g_gcnt[g] = 0.0f;

    // grid-stride zero of deg/agg1 + allocator
    int tid = g * 32 + lt;
    int stride = N_GRAPHS * 32;
    for (int j = tid; j < N_NODES; j += stride) { g_deg[j] = 0; g_agg1[j] = 0.0f; }
    if (tid == 0) g_alloc = 0;
}

extern "C" void kernel_launch(void* const* d_in, const int* in_sizes, int n_in,
                              void* d_out, int out_size) {
    const float* x    = (const float*)d_in[0];
    const int*   ei   = (const int*)d_in[1];
    const int*   bat  = (const int*)d_in[2];
    const float* W1l  = (const float*)d_in[3];
    const float* b1   = (const float*)d_in[4];
    const float* W1r  = (const float*)d_in[5];
    const float* W2l  = (const float*)d_in[6];
    const float* b2   = (const float*)d_in[7];
    const float* W2r  = (const float*)d_in[8];
    const float* Wc   = (const float*)d_in[9];
    const float* bc   = (const float*)d_in[10];
    float*       out  = (float*)d_out;

    (void)in_sizes; (void)n_in; (void)out_size;

    hist_kernel<<<(N_EDGES + 255) / 256, 256>>>(ei, bat, x);      // #1
    scan_alloc_kernel<<<NBLK, 256>>>(x);                           // #2
    scatter_kernel<<<(N_EDGES + 255) / 256, 256>>>(ei);            // #3
    h2pool_gemm<<<(N_NODES + 63) / 64, 256>>>(bat, W2l, b2, W2r,   // #4 (ncu target)
                                              W1l, b1, W1r);
    final_kernel<<<N_GRAPHS, 32>>>(Wc, bc, out);                   // #5
}